// round 5
// baseline (speedup 1.0000x reference)
#include <cuda_runtime.h>
#include <cuda_bf16.h>

#define BATCH 2048
#define LR 49          // K_REG
#define DIM 2048

// __device__ scratch (allocation-free)
__device__ __nv_bfloat16 wv_bf[LR * DIM];        // bf16 copy of W_v
__device__ float part_scr[16 * BATCH * LR];      // [type*8+ksp][batch][k] partials
__device__ float g_scr[BATCH * LR];              // h_t @ W_g^T (reduced)
__device__ float sent_scr[BATCH];                // sentinel logit

// ---------------------------------------------------------------------------
// Kernel 1: split-K MMA GEMM. grid 256:
//   type = bid>>7 (0: h_t@W_g^T, 1: s_t@W_s^T), btile = (bid>>3)&15, ksp = bid&7
// Each CTA: M=128 batches, N=56 (49 used), K = 256 (4 chunks of 64).
// Partial results -> part_scr. Also W_v -> bf16 (98 float4 per CTA).
// ---------------------------------------------------------------------------
__global__ __launch_bounds__(256) void k1(
    const float* __restrict__ h_t, const float* __restrict__ s_t,
    const float* __restrict__ W_v, const float* __restrict__ W_g,
    const float* __restrict__ W_s)
{
    __shared__ __align__(16) unsigned char raw[29184];
    __nv_bfloat16* A_sm = (__nv_bfloat16*)raw;            // 128 x 72 bf16
    __nv_bfloat16* B_sm = (__nv_bfloat16*)(raw + 18432);  // 56 x 72 bf16
    unsigned* Au = (unsigned*)A_sm;
    unsigned* Bu = (unsigned*)B_sm;
    float (*P)[57] = (float (*)[57])raw;                  // 128 x 57 fp32 (alias)

    const int tid = threadIdx.x;
    const int warp = tid >> 5, lane = tid & 31;
    const int typ = blockIdx.x >> 7;
    const int btile = (blockIdx.x >> 3) & 15;
    const int ksp = blockIdx.x & 7;
    const int b0 = btile * 128;
    const int kbase = ksp * 256;                 // float column offset
    const float* X = typ ? s_t : h_t;
    const float* W = typ ? W_s : W_g;
    float* dst = part_scr + (size_t)(typ * 8 + ksp) * BATCH * LR;

    // W_v -> bf16, 98 float4 per CTA
    if (tid < 98) {
        int i = blockIdx.x * 98 + tid;
        float4 v = ((const float4*)W_v)[i];
        __nv_bfloat162 lo = __floats2bfloat162_rn(v.x, v.y);
        __nv_bfloat162 hi = __floats2bfloat162_rn(v.z, v.w);
        __nv_bfloat162* d = (__nv_bfloat162*)(wv_bf) + (size_t)i * 2;
        d[0] = lo; d[1] = hi;
    }

    // zero smem (pad cols / pad rows stay zero)
    for (int i = tid; i < 29184 / 4; i += 256) ((unsigned*)raw)[i] = 0u;

    // prefetch slot descriptors
    const float* asrc[8]; int adst[8];
    #pragma unroll
    for (int s = 0; s < 8; s++) {
        int a = s * 256 + tid;               // 0..2047
        int row = a >> 4, c4 = a & 15;
        asrc[s] = X + (size_t)(b0 + row) * DIM + kbase + c4 * 4;
        adst[s] = row * 72 + c4 * 4;
    }
    const float* bsrc[4]; int bdst[4]; bool bact[4]; bool bzero[4];
    #pragma unroll
    for (int s = 0; s < 4; s++) {
        int idx = s * 256 + tid;             // 0..1023, active < 896
        bact[s] = (idx < 896);
        int row = idx >> 4, c4 = idx & 15;
        bzero[s] = (row >= LR);
        int rowc = (row < LR) ? row : 0;
        bsrc[s] = W + (size_t)rowc * DIM + kbase + c4 * 4;
        bdst[s] = row * 72 + c4 * 4;
    }

    float acc[7][4];
    #pragma unroll
    for (int j = 0; j < 7; j++) { acc[j][0]=acc[j][1]=acc[j][2]=acc[j][3]=0.f; }

    float4 ra[8], rbv[4];
    #pragma unroll
    for (int s = 0; s < 8; s++) ra[s] = *(const float4*)(asrc[s]);
    #pragma unroll
    for (int s = 0; s < 4; s++) if (bact[s]) rbv[s] = *(const float4*)(bsrc[s]);
    __syncthreads();   // zero-fill done

    #pragma unroll 1
    for (int ch = 0; ch < 4; ch++) {
        #pragma unroll
        for (int s = 0; s < 8; s++) {
            __nv_bfloat162 p0 = __floats2bfloat162_rn(ra[s].x, ra[s].y);
            __nv_bfloat162 p1 = __floats2bfloat162_rn(ra[s].z, ra[s].w);
            __nv_bfloat162* d = (__nv_bfloat162*)(A_sm + adst[s]);
            d[0] = p0; d[1] = p1;
        }
        #pragma unroll
        for (int s = 0; s < 4; s++) {
            if (bact[s]) {
                float4 v = bzero[s] ? make_float4(0.f,0.f,0.f,0.f) : rbv[s];
                __nv_bfloat162 p0 = __floats2bfloat162_rn(v.x, v.y);
                __nv_bfloat162 p1 = __floats2bfloat162_rn(v.z, v.w);
                __nv_bfloat162* d = (__nv_bfloat162*)(B_sm + bdst[s]);
                d[0] = p0; d[1] = p1;
            }
        }
        __syncthreads();
        if (ch + 1 < 4) {
            #pragma unroll
            for (int s = 0; s < 8; s++) ra[s] = *(const float4*)(asrc[s] + (ch + 1) * 64);
            #pragma unroll
            for (int s = 0; s < 4; s++) if (bact[s]) rbv[s] = *(const float4*)(bsrc[s] + (ch + 1) * 64);
        }
        #pragma unroll
        for (int st = 0; st < 4; st++) {
            int baseu = st * 8;
            int ai = (warp * 16 + (lane >> 2)) * 36 + baseu + (lane & 3);
            unsigned a0 = Au[ai];
            unsigned a1 = Au[ai + 8 * 36];
            unsigned a2 = Au[ai + 4];
            unsigned a3 = Au[ai + 8 * 36 + 4];
            #pragma unroll
            for (int j = 0; j < 7; j++) {
                int bidx = (j * 8 + (lane >> 2)) * 36 + baseu + (lane & 3);
                unsigned bb0 = Bu[bidx];
                unsigned bb1 = Bu[bidx + 4];
                asm volatile(
                    "mma.sync.aligned.m16n8k16.row.col.f32.bf16.bf16.f32 "
                    "{%0,%1,%2,%3}, {%4,%5,%6,%7}, {%8,%9}, {%0,%1,%2,%3};\n"
                    : "+f"(acc[j][0]), "+f"(acc[j][1]), "+f"(acc[j][2]), "+f"(acc[j][3])
                    : "r"(a0), "r"(a1), "r"(a2), "r"(a3), "r"(bb0), "r"(bb1));
            }
        }
        __syncthreads();
    }

    // epilogue: acc -> P (alias) -> gmem partials
    #pragma unroll
    for (int j = 0; j < 7; j++) {
        int r = warp * 16 + (lane >> 2);
        int c = j * 8 + 2 * (lane & 3);
        P[r][c]         = acc[j][0];
        P[r][c + 1]     = acc[j][1];
        P[r + 8][c]     = acc[j][2];
        P[r + 8][c + 1] = acc[j][3];
    }
    __syncthreads();
    for (int idx = tid; idx < 128 * LR; idx += 256) {
        int row = idx / LR, k = idx - row * LR;
        dst[(size_t)(b0 + row) * LR + k] = P[row][k];
    }
}

// ---------------------------------------------------------------------------
// Kernel 1b: reduce split-K partials -> g_scr; sent[b] from g + S
// grid 256, block 256: warp per batch
// ---------------------------------------------------------------------------
__global__ __launch_bounds__(256) void k1b(const float* __restrict__ w_h_s)
{
    const int warp = threadIdx.x >> 5, lane = threadIdx.x & 31;
    const int b = blockIdx.x * 8 + warp;
    float s = 0.f;

    if (lane < LR) {
        float g = 0.f, S = 0.f;
        #pragma unroll
        for (int i = 0; i < 8; i++) {
            g += part_scr[((size_t)i * BATCH + b) * LR + lane];
            S += part_scr[((size_t)(8 + i) * BATCH + b) * LR + lane];
        }
        g_scr[(size_t)b * LR + lane] = g;
        s = tanhf(g + S) * w_h_s[lane];
    }
    if (lane + 32 < LR) {
        float g = 0.f, S = 0.f;
        #pragma unroll
        for (int i = 0; i < 8; i++) {
            g += part_scr[((size_t)i * BATCH + b) * LR + lane + 32];
            S += part_scr[((size_t)(8 + i) * BATCH + b) * LR + lane + 32];
        }
        g_scr[(size_t)b * LR + lane + 32] = g;
        s += tanhf(g + S) * w_h_s[lane + 32];
    }
    #pragma unroll
    for (int o = 16; o > 0; o >>= 1) s += __shfl_xor_sync(0xffffffffu, s, o);
    if (lane == 0) sent_scr[b] = s;
}

// ---------------------------------------------------------------------------
// Kernel 2: fused W_vV GEMM (bf16 mma.sync, N=56) + tanh/softmax + c_t + out
// grid 1024 (2 batches per CTA), block 256 (8 warps), target 3 CTAs/SM
// ---------------------------------------------------------------------------
__global__ __launch_bounds__(256, 3) void k2(
    const float* __restrict__ V, const float* __restrict__ h_t,
    const float* __restrict__ s_t, const float* __restrict__ w_h,
    float* __restrict__ out)
{
    __shared__ __align__(16) unsigned char smraw[35088];

    const int tid = threadIdx.x;
    const int warp = tid >> 5, lane = tid & 31;
    const int b0 = blockIdx.x * 2, b1 = b0 + 1;

    __nv_bfloat16* A_sm = (__nv_bfloat16*)smraw;             // 128 x 72 bf16
    __nv_bfloat16* B_sm = (__nv_bfloat16*)(smraw + 18432);   // 64 x 72 bf16
    unsigned* Au = (unsigned*)A_sm;
    unsigned* Bu = (unsigned*)B_sm;
    float (*Wv)[65] = (float (*)[65])smraw;                  // aliases A/B after GEMM
    float* gk      = (float*)(smraw + 33280);   // [128]
    float* wh      = (float*)(smraw + 33792);   // [64]
    float* zsm     = (float*)(smraw + 34048);   // [128]
    float* alpha_s = (float*)(smraw + 34560);   // [128]
    float* bet     = (float*)(smraw + 35072);   // [2]

    for (int i = tid; i < (18432 + 9216) / 4; i += 256) ((unsigned*)smraw)[i] = 0u;

    const float* Vb0 = V + (size_t)b0 * LR * DIM;

    // compact 32-bit offset descriptors (element offsets from Vb0 / wv_bf)
    unsigned aoff[7]; int adst[7]; bool aact[7];
    #pragma unroll
    for (int s = 0; s < 7; s++) {
        int a = s * 256 + tid;
        aact[s] = (a < 1568);
        int batch = (a >= 784) ? 1 : 0;
        int idx = a - 784 * batch;
        int row = idx >> 4, c4 = idx & 15;
        if (!aact[s]) { batch = 0; row = 0; c4 = 0; }
        aoff[s] = (unsigned)(batch * LR * DIM + row * DIM + c4 * 4);
        adst[s] = (batch * 64 + row) * 72 + c4 * 4;
    }
    unsigned boff[2]; int bdst[2]; bool bact[2];
    #pragma unroll
    for (int s = 0; s < 2; s++) {
        int bidx = s * 256 + tid;
        bact[s] = (bidx < 392);
        int row = bidx >> 3, q = bidx & 7;
        if (!bact[s]) { row = 0; q = 0; }
        boff[s] = (unsigned)(row * DIM + q * 8);
        bdst[s] = row * 72 + q * 8;
    }

    float acc[7][4];
    #pragma unroll
    for (int j = 0; j < 7; j++) { acc[j][0]=acc[j][1]=acc[j][2]=acc[j][3]=0.f; }

    float4 ra[7]; uint4 rb[2];
    #pragma unroll
    for (int s = 0; s < 7; s++) if (aact[s]) ra[s] = *(const float4*)(Vb0 + aoff[s]);
    #pragma unroll
    for (int s = 0; s < 2; s++) if (bact[s]) rb[s] = *(const uint4*)(wv_bf + boff[s]);

    __syncthreads();   // zero-fill complete

    #pragma unroll 1
    for (int ch = 0; ch < 32; ch++) {
        #pragma unroll
        for (int s = 0; s < 7; s++) {
            if (aact[s]) {
                __nv_bfloat162 p0 = __floats2bfloat162_rn(ra[s].x, ra[s].y);
                __nv_bfloat162 p1 = __floats2bfloat162_rn(ra[s].z, ra[s].w);
                __nv_bfloat162* d = (__nv_bfloat162*)(A_sm + adst[s]);
                d[0] = p0; d[1] = p1;
            }
        }
        #pragma unroll
        for (int s = 0; s < 2; s++)
            if (bact[s]) *(uint4*)(B_sm + bdst[s]) = rb[s];
        __syncthreads();

        if (ch + 1 < 32) {
            #pragma unroll
            for (int s = 0; s < 7; s++)
                if (aact[s]) ra[s] = *(const float4*)(Vb0 + aoff[s] + (ch + 1) * 64);
            #pragma unroll
            for (int s = 0; s < 2; s++)
                if (bact[s]) rb[s] = *(const uint4*)(wv_bf + boff[s] + (ch + 1) * 64);
        }

        #pragma unroll
        for (int st = 0; st < 4; st++) {
            int baseu = st * 8;
            int ai = (warp * 16 + (lane >> 2)) * 36 + baseu + (lane & 3);
            unsigned a0 = Au[ai];
            unsigned a1 = Au[ai + 8 * 36];
            unsigned a2 = Au[ai + 4];
            unsigned a3 = Au[ai + 8 * 36 + 4];
            #pragma unroll
            for (int j = 0; j < 7; j++) {
                int bidx = (j * 8 + (lane >> 2)) * 36 + baseu + (lane & 3);
                unsigned bb0 = Bu[bidx];
                unsigned bb1 = Bu[bidx + 4];
                asm volatile(
                    "mma.sync.aligned.m16n8k16.row.col.f32.bf16.bf16.f32 "
                    "{%0,%1,%2,%3}, {%4,%5,%6,%7}, {%8,%9}, {%0,%1,%2,%3};\n"
                    : "+f"(acc[j][0]), "+f"(acc[j][1]), "+f"(acc[j][2]), "+f"(acc[j][3])
                    : "r"(a0), "r"(a1), "r"(a2), "r"(a3), "r"(bb0), "r"(bb1));
            }
        }
        __syncthreads();
    }

    // ---- epilogue ----
    #pragma unroll
    for (int j = 0; j < 7; j++) {
        int r = warp * 16 + (lane >> 2);
        int c = j * 8 + 2 * (lane & 3);
        Wv[r][c]         = acc[j][0];
        Wv[r][c + 1]     = acc[j][1];
        Wv[r + 8][c]     = acc[j][2];
        Wv[r + 8][c + 1] = acc[j][3];
    }
    if (tid < LR) {
        gk[tid]      = g_scr[(size_t)b0 * LR + tid];
        gk[64 + tid] = g_scr[(size_t)b1 * LR + tid];
        wh[tid]      = w_h[tid];
    }
    __syncthreads();

    {
        int lv = tid >> 1, q = tid & 1;
        int gb = lv & 64;
        float z = 0.f;
        for (int k = q; k < LR; k += 2)
            z += tanhf(Wv[lv][k] + gk[gb + k]) * wh[k];
        z += __shfl_xor_sync(0xffffffffu, z, 1);
        if (q == 0) zsm[lv] = z;
    }
    __syncthreads();

    if (warp < 2) {
        float v0 = (lane < LR) ? zsm[warp * 64 + lane] : -1e30f;
        float v1 = -1e30f;
        if (lane + 32 < LR)       v1 = zsm[warp * 64 + lane + 32];
        else if (lane + 32 == LR) v1 = sent_scr[b0 + warp];
        float m = fmaxf(v0, v1);
        #pragma unroll
        for (int o = 16; o > 0; o >>= 1) m = fmaxf(m, __shfl_xor_sync(0xffffffffu, m, o));
        float e0 = __expf(v0 - m), e1 = __expf(v1 - m);
        float s = e0 + e1;
        #pragma unroll
        for (int o = 16; o > 0; o >>= 1) s += __shfl_xor_sync(0xffffffffu, s, o);
        float inv = 1.f / s;
        if (lane < LR)       alpha_s[warp * 64 + lane]      = e0 * inv;
        if (lane + 32 < LR)  alpha_s[warp * 64 + lane + 32] = e1 * inv;
        if (lane == 17)      bet[warp] = e1 * inv;
    }
    __syncthreads();

    // pass 2: c_t + output
    #pragma unroll 1
    for (int pbv = 0; pbv < 2; pbv++) {
        const float* Vb = Vb0 + (size_t)pbv * LR * DIM;
        const float* ap = alpha_s + pbv * 64;
        float c0x = 0.f, c0y = 0.f, c0z = 0.f, c0w = 0.f;
        float c1x = 0.f, c1y = 0.f, c1z = 0.f, c1w = 0.f;
        #pragma unroll 7
        for (int l = 0; l < LR; l++) {
            float a = ap[l];
            float4 v0 = *(const float4*)(Vb + (size_t)l * DIM + tid * 4);
            float4 v1 = *(const float4*)(Vb + (size_t)l * DIM + 1024 + tid * 4);
            c0x += a * v0.x; c0y += a * v0.y; c0z += a * v0.z; c0w += a * v0.w;
            c1x += a * v1.x; c1y += a * v1.y; c1z += a * v1.z; c1w += a * v1.w;
        }
        int b = pbv ? b1 : b0;
        float be = bet[pbv];
        float om = 1.f - be;
        {
            float4 s4 = *(const float4*)(s_t + (size_t)b * DIM + tid * 4);
            float4 h4 = *(const float4*)(h_t + (size_t)b * DIM + tid * 4);
            float4 o;
            o.x = be * s4.x + om * c0x + h4.x;
            o.y = be * s4.y + om * c0y + h4.y;
            o.z = be * s4.z + om * c0z + h4.z;
            o.w = be * s4.w + om * c0w + h4.w;
            *(float4*)(out + (size_t)b * DIM + tid * 4) = o;
        }
        {
            float4 s4 = *(const float4*)(s_t + (size_t)b * DIM + 1024 + tid * 4);
            float4 h4 = *(const float4*)(h_t + (size_t)b * DIM + 1024 + tid * 4);
            float4 o;
            o.x = be * s4.x + om * c1x + h4.x;
            o.y = be * s4.y + om * c1y + h4.y;
            o.z = be * s4.z + om * c1z + h4.z;
            o.w = be * s4.w + om * c1w + h4.w;
            *(float4*)(out + (size_t)b * DIM + 1024 + tid * 4) = o;
        }
    }
}

extern "C" void kernel_launch(void* const* d_in, const int* in_sizes, int n_in,
                              void* d_out, int out_size) {
    const float* V     = (const float*)d_in[0];
    const float* h_t   = (const float*)d_in[1];
    const float* s_t   = (const float*)d_in[2];
    const float* W_v   = (const float*)d_in[3];
    const float* W_g   = (const float*)d_in[4];
    const float* W_s   = (const float*)d_in[5];
    const float* w_h   = (const float*)d_in[6];
    const float* w_h_s = (const float*)d_in[7];
    float* out = (float*)d_out;

    k1<<<256, 256>>>(h_t, s_t, W_v, W_g, W_s);
    k1b<<<256, 256>>>(w_h_s);
    k2<<<1024, 256>>>(V, h_t, s_t, w_h, out);
}

// round 7
// speedup vs baseline: 1.2691x; 1.2691x over previous
#include <cuda_runtime.h>
#include <cuda_bf16.h>

#define BATCH 2048
#define LR 49          // K_REG
#define DIM 2048

// __device__ scratch (allocation-free)
__device__ __nv_bfloat16 wv_bf[LR * DIM];        // bf16 copy of W_v
__device__ float part_scr[16 * BATCH * LR];      // [type*8+ksp][batch][k] partials

// ---------------------------------------------------------------------------
// Kernel 1: split-K MMA GEMM. grid 256:
//   type = bid>>7 (0: h_t@W_g^T, 1: s_t@W_s^T), btile = (bid>>3)&15, ksp = bid&7
// Each CTA: M=128 batches, N=56 (49 used), K = 256 (4 chunks of 64).
// Partial results -> part_scr. Also W_v -> bf16 (98 float4 per CTA).
// ---------------------------------------------------------------------------
__global__ __launch_bounds__(256) void k1(
    const float* __restrict__ h_t, const float* __restrict__ s_t,
    const float* __restrict__ W_v, const float* __restrict__ W_g,
    const float* __restrict__ W_s)
{
    __shared__ __align__(16) unsigned char raw[29184];
    __nv_bfloat16* A_sm = (__nv_bfloat16*)raw;            // 128 x 72 bf16
    __nv_bfloat16* B_sm = (__nv_bfloat16*)(raw + 18432);  // 56 x 72 bf16
    unsigned* Au = (unsigned*)A_sm;
    unsigned* Bu = (unsigned*)B_sm;
    float (*P)[57] = (float (*)[57])raw;                  // 128 x 57 fp32 (alias)

    const int tid = threadIdx.x;
    const int warp = tid >> 5, lane = tid & 31;
    const int typ = blockIdx.x >> 7;
    const int btile = (blockIdx.x >> 3) & 15;
    const int ksp = blockIdx.x & 7;
    const int b0 = btile * 128;
    const int kbase = ksp * 256;                 // float column offset
    const float* X = typ ? s_t : h_t;
    const float* W = typ ? W_s : W_g;
    float* dst = part_scr + (size_t)(typ * 8 + ksp) * BATCH * LR;

    // W_v -> bf16, 98 float4 per CTA
    if (tid < 98) {
        int i = blockIdx.x * 98 + tid;
        float4 v = ((const float4*)W_v)[i];
        __nv_bfloat162 lo = __floats2bfloat162_rn(v.x, v.y);
        __nv_bfloat162 hi = __floats2bfloat162_rn(v.z, v.w);
        __nv_bfloat162* d = (__nv_bfloat162*)(wv_bf) + (size_t)i * 2;
        d[0] = lo; d[1] = hi;
    }

    // zero smem (pad cols / pad rows stay zero)
    for (int i = tid; i < 29184 / 4; i += 256) ((unsigned*)raw)[i] = 0u;

    // prefetch slot descriptors
    const float* asrc[8]; int adst[8];
    #pragma unroll
    for (int s = 0; s < 8; s++) {
        int a = s * 256 + tid;               // 0..2047
        int row = a >> 4, c4 = a & 15;
        asrc[s] = X + (size_t)(b0 + row) * DIM + kbase + c4 * 4;
        adst[s] = row * 72 + c4 * 4;
    }
    const float* bsrc[4]; int bdst[4]; bool bact[4]; bool bzero[4];
    #pragma unroll
    for (int s = 0; s < 4; s++) {
        int idx = s * 256 + tid;             // 0..1023, active < 896
        bact[s] = (idx < 896);
        int row = idx >> 4, c4 = idx & 15;
        bzero[s] = (row >= LR);
        int rowc = (row < LR) ? row : 0;
        bsrc[s] = W + (size_t)rowc * DIM + kbase + c4 * 4;
        bdst[s] = row * 72 + c4 * 4;
    }

    float acc[7][4];
    #pragma unroll
    for (int j = 0; j < 7; j++) { acc[j][0]=acc[j][1]=acc[j][2]=acc[j][3]=0.f; }

    float4 ra[8], rbv[4];
    #pragma unroll
    for (int s = 0; s < 8; s++) ra[s] = *(const float4*)(asrc[s]);
    #pragma unroll
    for (int s = 0; s < 4; s++) if (bact[s]) rbv[s] = *(const float4*)(bsrc[s]);
    __syncthreads();   // zero-fill done

    #pragma unroll 1
    for (int ch = 0; ch < 4; ch++) {
        #pragma unroll
        for (int s = 0; s < 8; s++) {
            __nv_bfloat162 p0 = __floats2bfloat162_rn(ra[s].x, ra[s].y);
            __nv_bfloat162 p1 = __floats2bfloat162_rn(ra[s].z, ra[s].w);
            __nv_bfloat162* d = (__nv_bfloat162*)(A_sm + adst[s]);
            d[0] = p0; d[1] = p1;
        }
        #pragma unroll
        for (int s = 0; s < 4; s++) {
            if (bact[s]) {
                float4 v = bzero[s] ? make_float4(0.f,0.f,0.f,0.f) : rbv[s];
                __nv_bfloat162 p0 = __floats2bfloat162_rn(v.x, v.y);
                __nv_bfloat162 p1 = __floats2bfloat162_rn(v.z, v.w);
                __nv_bfloat162* d = (__nv_bfloat162*)(B_sm + bdst[s]);
                d[0] = p0; d[1] = p1;
            }
        }
        __syncthreads();
        if (ch + 1 < 4) {
            #pragma unroll
            for (int s = 0; s < 8; s++) ra[s] = *(const float4*)(asrc[s] + (ch + 1) * 64);
            #pragma unroll
            for (int s = 0; s < 4; s++) if (bact[s]) rbv[s] = *(const float4*)(bsrc[s] + (ch + 1) * 64);
        }
        #pragma unroll
        for (int st = 0; st < 4; st++) {
            int baseu = st * 8;
            int ai = (warp * 16 + (lane >> 2)) * 36 + baseu + (lane & 3);
            unsigned a0 = Au[ai];
            unsigned a1 = Au[ai + 8 * 36];
            unsigned a2 = Au[ai + 4];
            unsigned a3 = Au[ai + 8 * 36 + 4];
            #pragma unroll
            for (int j = 0; j < 7; j++) {
                int bidx = (j * 8 + (lane >> 2)) * 36 + baseu + (lane & 3);
                unsigned bb0 = Bu[bidx];
                unsigned bb1 = Bu[bidx + 4];
                asm volatile(
                    "mma.sync.aligned.m16n8k16.row.col.f32.bf16.bf16.f32 "
                    "{%0,%1,%2,%3}, {%4,%5,%6,%7}, {%8,%9}, {%0,%1,%2,%3};\n"
                    : "+f"(acc[j][0]), "+f"(acc[j][1]), "+f"(acc[j][2]), "+f"(acc[j][3])
                    : "r"(a0), "r"(a1), "r"(a2), "r"(a3), "r"(bb0), "r"(bb1));
            }
        }
        __syncthreads();
    }

    // epilogue: acc -> P (alias) -> gmem partials
    #pragma unroll
    for (int j = 0; j < 7; j++) {
        int r = warp * 16 + (lane >> 2);
        int c = j * 8 + 2 * (lane & 3);
        P[r][c]         = acc[j][0];
        P[r][c + 1]     = acc[j][1];
        P[r + 8][c]     = acc[j][2];
        P[r + 8][c + 1] = acc[j][3];
    }
    __syncthreads();
    for (int idx = tid; idx < 128 * LR; idx += 256) {
        int row = idx / LR, k = idx - row * LR;
        dst[(size_t)(b0 + row) * LR + k] = P[row][k];
    }
}

// ---------------------------------------------------------------------------
// Kernel 2: fused W_vV GEMM (bf16 mma.sync, N=56, 1-deep register prefetch)
//           + inline split-K reduction of g/S partials + sent
//           + tanh/softmax + c_t + output
// grid 1024 (2 batches per CTA), block 256 (8 warps); natural occupancy
// ---------------------------------------------------------------------------
__global__ __launch_bounds__(256) void k2(
    const float* __restrict__ V, const float* __restrict__ h_t,
    const float* __restrict__ s_t, const float* __restrict__ w_h,
    const float* __restrict__ w_h_s, float* __restrict__ out)
{
    __shared__ __align__(16) unsigned char smraw[35600];

    const int tid = threadIdx.x;
    const int warp = tid >> 5, lane = tid & 31;
    const int b0 = blockIdx.x * 2, b1 = b0 + 1;

    __nv_bfloat16* A_sm = (__nv_bfloat16*)smraw;             // 128 x 72 bf16
    __nv_bfloat16* B_sm = (__nv_bfloat16*)(smraw + 18432);   // 64 x 72 bf16
    unsigned* Au = (unsigned*)A_sm;
    unsigned* Bu = (unsigned*)B_sm;
    float (*Wv)[65] = (float (*)[65])smraw;                  // aliases A/B after GEMM
    float* gk      = (float*)(smraw + 33280);   // [128]
    float* wh      = (float*)(smraw + 33792);   // [64]
    float* zsm     = (float*)(smraw + 34048);   // [128]
    float* alpha_s = (float*)(smraw + 34560);   // [128]
    float* bet     = (float*)(smraw + 35072);   // [2]
    float* ssm     = (float*)(smraw + 35088);   // [128] tanh(g+S)*w_h_s terms

    for (int i = tid; i < (18432 + 9216) / 4; i += 256) ((unsigned*)smraw)[i] = 0u;

    const float* Vb0 = V + (size_t)b0 * LR * DIM;
    const float* Vb1 = V + (size_t)b1 * LR * DIM;

    // per-thread prefetch slot descriptors (R2-proven layout)
    const float* asrc[7]; int adst[7]; bool aact[7];
    #pragma unroll
    for (int s = 0; s < 7; s++) {
        int a = s * 256 + tid;
        aact[s] = (a < 1568);
        int batch = (a >= 784) ? 1 : 0;
        int idx = a - 784 * batch;
        int row = idx >> 4, c4 = idx & 15;
        if (!aact[s]) { row = 0; c4 = 0; }
        asrc[s] = (batch ? Vb1 : Vb0) + (size_t)row * DIM + c4 * 4;
        adst[s] = (batch * 64 + row) * 72 + c4 * 4;
    }
    const __nv_bfloat16* bsrc[2]; int bdst[2]; bool bact[2];
    #pragma unroll
    for (int s = 0; s < 2; s++) {
        int bidx = s * 256 + tid;
        bact[s] = (bidx < 392);
        int row = bidx >> 3, q = bidx & 7;
        if (!bact[s]) { row = 0; q = 0; }
        bsrc[s] = wv_bf + (size_t)row * DIM + q * 8;
        bdst[s] = row * 72 + q * 8;
    }

    float acc[7][4];
    #pragma unroll
    for (int j = 0; j < 7; j++) { acc[j][0]=acc[j][1]=acc[j][2]=acc[j][3]=0.f; }

    float4 ra[7]; uint4 rb[2];
    #pragma unroll
    for (int s = 0; s < 7; s++) if (aact[s]) ra[s] = *(const float4*)(asrc[s]);
    #pragma unroll
    for (int s = 0; s < 2; s++) if (bact[s]) rb[s] = *(const uint4*)(bsrc[s]);

    __syncthreads();   // zero-fill complete

    #pragma unroll 1
    for (int ch = 0; ch < 32; ch++) {
        #pragma unroll
        for (int s = 0; s < 7; s++) {
            if (aact[s]) {
                __nv_bfloat162 p0 = __floats2bfloat162_rn(ra[s].x, ra[s].y);
                __nv_bfloat162 p1 = __floats2bfloat162_rn(ra[s].z, ra[s].w);
                __nv_bfloat162* d = (__nv_bfloat162*)(A_sm + adst[s]);
                d[0] = p0; d[1] = p1;
            }
        }
        #pragma unroll
        for (int s = 0; s < 2; s++)
            if (bact[s]) *(uint4*)(B_sm + bdst[s]) = rb[s];
        __syncthreads();

        // next chunk's globals (consumed after the MMAs)
        if (ch + 1 < 32) {
            #pragma unroll
            for (int s = 0; s < 7; s++)
                if (aact[s]) ra[s] = *(const float4*)(asrc[s] + (ch + 1) * 64);
            #pragma unroll
            for (int s = 0; s < 2; s++)
                if (bact[s]) rb[s] = *(const uint4*)(bsrc[s] + (ch + 1) * 64);
        }

        #pragma unroll
        for (int st = 0; st < 4; st++) {
            int baseu = st * 8;
            int ai = (warp * 16 + (lane >> 2)) * 36 + baseu + (lane & 3);
            unsigned a0 = Au[ai];
            unsigned a1 = Au[ai + 8 * 36];
            unsigned a2 = Au[ai + 4];
            unsigned a3 = Au[ai + 8 * 36 + 4];
            #pragma unroll
            for (int j = 0; j < 7; j++) {
                int bidx = (j * 8 + (lane >> 2)) * 36 + baseu + (lane & 3);
                unsigned bb0 = Bu[bidx];
                unsigned bb1 = Bu[bidx + 4];
                asm volatile(
                    "mma.sync.aligned.m16n8k16.row.col.f32.bf16.bf16.f32 "
                    "{%0,%1,%2,%3}, {%4,%5,%6,%7}, {%8,%9}, {%0,%1,%2,%3};\n"
                    : "+f"(acc[j][0]), "+f"(acc[j][1]), "+f"(acc[j][2]), "+f"(acc[j][3])
                    : "r"(a0), "r"(a1), "r"(a2), "r"(a3), "r"(bb0), "r"(bb1));
            }
        }
        __syncthreads();
    }

    // ---- epilogue ----
    #pragma unroll
    for (int j = 0; j < 7; j++) {
        int r = warp * 16 + (lane >> 2);
        int c = j * 8 + 2 * (lane & 3);
        Wv[r][c]         = acc[j][0];
        Wv[r][c + 1]     = acc[j][1];
        Wv[r + 8][c]     = acc[j][2];
        Wv[r + 8][c + 1] = acc[j][3];
    }
    // inline split-K reduction: g = sum partials(type0), S = sum partials(type1)
    if (tid < 2 * LR) {
        int bb = (tid >= LR) ? 1 : 0;
        int k = tid - bb * LR;
        int b = b0 + bb;
        float g = 0.f, S = 0.f;
        #pragma unroll
        for (int i = 0; i < 8; i++) {
            g += part_scr[((size_t)i * BATCH + b) * LR + k];
            S += part_scr[((size_t)(8 + i) * BATCH + b) * LR + k];
        }
        gk[bb * 64 + k]  = g;
        ssm[bb * 64 + k] = tanhf(g + S) * w_h_s[k];
    }
    if (tid < LR) wh[tid] = w_h[tid];
    __syncthreads();

    // z_t[l] = sum_k tanh(WvV[l,k] + g[k]) * w_h[k]
    {
        int lv = tid >> 1, q = tid & 1;
        int gb = lv & 64;
        float z = 0.f;
        for (int k = q; k < LR; k += 2)
            z += tanhf(Wv[lv][k] + gk[gb + k]) * wh[k];
        z += __shfl_xor_sync(0xffffffffu, z, 1);
        if (q == 0) zsm[lv] = z;
    }
    __syncthreads();

    // softmax over 50 logits, warps 0/1 (one per batch); sent reduced inline
    if (warp < 2) {
        float sp = (lane < LR) ? ssm[warp * 64 + lane] : 0.f;
        if (lane + 32 < LR) sp += ssm[warp * 64 + lane + 32];
        #pragma unroll
        for (int o = 16; o > 0; o >>= 1) sp += __shfl_xor_sync(0xffffffffu, sp, o);
        float sent = sp;   // uniform across warp

        float v0 = (lane < LR) ? zsm[warp * 64 + lane] : -1e30f;
        float v1 = -1e30f;
        if (lane + 32 < LR)       v1 = zsm[warp * 64 + lane + 32];
        else if (lane + 32 == LR) v1 = sent;
        float m = fmaxf(v0, v1);
        #pragma unroll
        for (int o = 16; o > 0; o >>= 1) m = fmaxf(m, __shfl_xor_sync(0xffffffffu, m, o));
        float e0 = __expf(v0 - m), e1 = __expf(v1 - m);
        float s = e0 + e1;
        #pragma unroll
        for (int o = 16; o > 0; o >>= 1) s += __shfl_xor_sync(0xffffffffu, s, o);
        float inv = 1.f / s;
        if (lane < LR)       alpha_s[warp * 64 + lane]      = e0 * inv;
        if (lane + 32 < LR)  alpha_s[warp * 64 + lane + 32] = e1 * inv;
        if (lane == 17)      bet[warp] = e1 * inv;   // logit index 49
    }
    __syncthreads();

    // pass 2: c_t + output
    #pragma unroll 1
    for (int pbv = 0; pbv < 2; pbv++) {
        const float* Vb = pbv ? Vb1 : Vb0;
        const float* ap = alpha_s + pbv * 64;
        float c0x = 0.f, c0y = 0.f, c0z = 0.f, c0w = 0.f;
        float c1x = 0.f, c1y = 0.f, c1z = 0.f, c1w = 0.f;
        #pragma unroll 7
        for (int l = 0; l < LR; l++) {
            float a = ap[l];
            float4 v0 = *(const float4*)(Vb + (size_t)l * DIM + tid * 4);
            float4 v1 = *(const float4*)(Vb + (size_t)l * DIM + 1024 + tid * 4);
            c0x += a * v0.x; c0y += a * v0.y; c0z += a * v0.z; c0w += a * v0.w;
            c1x += a * v1.x; c1y += a * v1.y; c1z += a * v1.z; c1w += a * v1.w;
        }
        int b = pbv ? b1 : b0;
        float be = bet[pbv];
        float om = 1.f - be;
        {
            float4 s4 = *(const float4*)(s_t + (size_t)b * DIM + tid * 4);
            float4 h4 = *(const float4*)(h_t + (size_t)b * DIM + tid * 4);
            float4 o;
            o.x = be * s4.x + om * c0x + h4.x;
            o.y = be * s4.y + om * c0y + h4.y;
            o.z = be * s4.z + om * c0z + h4.z;
            o.w = be * s4.w + om * c0w + h4.w;
            *(float4*)(out + (size_t)b * DIM + tid * 4) = o;
        }
        {
            float4 s4 = *(const float4*)(s_t + (size_t)b * DIM + 1024 + tid * 4);
            float4 h4 = *(const float4*)(h_t + (size_t)b * DIM + 1024 + tid * 4);
            float4 o;
            o.x = be * s4.x + om * c1x + h4.x;
            o.y = be * s4.y + om * c1y + h4.y;
            o.z = be * s4.z + om * c1z + h4.z;
            o.w = be * s4.w + om * c1w + h4.w;
            *(float4*)(out + (size_t)b * DIM + 1024 + tid * 4) = o;
        }
    }
}

extern "C" void kernel_launch(void* const* d_in, const int* in_sizes, int n_in,
                              void* d_out, int out_size) {
    const float* V     = (const float*)d_in[0];
    const float* h_t   = (const float*)d_in[1];
    const float* s_t   = (const float*)d_in[2];
    const float* W_v   = (const float*)d_in[3];
    const float* W_g   = (const float*)d_in[4];
    const float* W_s   = (const float*)d_in[5];
    const float* w_h   = (const float*)d_in[6];
    const float* w_h_s = (const float*)d_in[7];
    float* out = (float*)d_out;

    k1<<<256, 256>>>(h_t, s_t, W_v, W_g, W_s);
    k2<<<1024, 256>>>(V, h_t, s_t, w_h, w_h_s, out);
}

// round 8
// speedup vs baseline: 1.2734x; 1.0033x over previous
#include <cuda_runtime.h>
#include <cuda_bf16.h>

#define BATCH 2048
#define LR 49          // K_REG
#define DIM 2048

// __device__ scratch (allocation-free)
__device__ __nv_bfloat16 wv_bf[LR * DIM];        // bf16 copy of W_v
__device__ float part_scr[16 * BATCH * LR];      // [type*8+ksp][batch][k] partials

// ---------------------------------------------------------------------------
// Kernel 1: split-K MMA GEMM (proven 12.7us). grid 256:
//   type = bid>>7 (0: h_t@W_g^T, 1: s_t@W_s^T), btile = (bid>>3)&15, ksp = bid&7
// ---------------------------------------------------------------------------
__global__ __launch_bounds__(256) void k1(
    const float* __restrict__ h_t, const float* __restrict__ s_t,
    const float* __restrict__ W_v, const float* __restrict__ W_g,
    const float* __restrict__ W_s)
{
    __shared__ __align__(16) unsigned char raw[29184];
    __nv_bfloat16* A_sm = (__nv_bfloat16*)raw;            // 128 x 72 bf16
    __nv_bfloat16* B_sm = (__nv_bfloat16*)(raw + 18432);  // 56 x 72 bf16
    unsigned* Au = (unsigned*)A_sm;
    unsigned* Bu = (unsigned*)B_sm;
    float (*P)[57] = (float (*)[57])raw;                  // 128 x 57 fp32 (alias)

    const int tid = threadIdx.x;
    const int warp = tid >> 5, lane = tid & 31;
    const int typ = blockIdx.x >> 7;
    const int btile = (blockIdx.x >> 3) & 15;
    const int ksp = blockIdx.x & 7;
    const int b0 = btile * 128;
    const int kbase = ksp * 256;
    const float* X = typ ? s_t : h_t;
    const float* W = typ ? W_s : W_g;
    float* dst = part_scr + (size_t)(typ * 8 + ksp) * BATCH * LR;

    if (tid < 98) {
        int i = blockIdx.x * 98 + tid;
        float4 v = ((const float4*)W_v)[i];
        __nv_bfloat162 lo = __floats2bfloat162_rn(v.x, v.y);
        __nv_bfloat162 hi = __floats2bfloat162_rn(v.z, v.w);
        __nv_bfloat162* d = (__nv_bfloat162*)(wv_bf) + (size_t)i * 2;
        d[0] = lo; d[1] = hi;
    }

    for (int i = tid; i < 29184 / 4; i += 256) ((unsigned*)raw)[i] = 0u;

    const float* asrc[8]; int adst[8];
    #pragma unroll
    for (int s = 0; s < 8; s++) {
        int a = s * 256 + tid;
        int row = a >> 4, c4 = a & 15;
        asrc[s] = X + (size_t)(b0 + row) * DIM + kbase + c4 * 4;
        adst[s] = row * 72 + c4 * 4;
    }
    const float* bsrc[4]; int bdst[4]; bool bact[4]; bool bzero[4];
    #pragma unroll
    for (int s = 0; s < 4; s++) {
        int idx = s * 256 + tid;
        bact[s] = (idx < 896);
        int row = idx >> 4, c4 = idx & 15;
        bzero[s] = (row >= LR);
        int rowc = (row < LR) ? row : 0;
        bsrc[s] = W + (size_t)rowc * DIM + kbase + c4 * 4;
        bdst[s] = row * 72 + c4 * 4;
    }

    float acc[7][4];
    #pragma unroll
    for (int j = 0; j < 7; j++) { acc[j][0]=acc[j][1]=acc[j][2]=acc[j][3]=0.f; }

    float4 ra[8], rbv[4];
    #pragma unroll
    for (int s = 0; s < 8; s++) ra[s] = *(const float4*)(asrc[s]);
    #pragma unroll
    for (int s = 0; s < 4; s++) if (bact[s]) rbv[s] = *(const float4*)(bsrc[s]);
    __syncthreads();

    #pragma unroll 1
    for (int ch = 0; ch < 4; ch++) {
        #pragma unroll
        for (int s = 0; s < 8; s++) {
            __nv_bfloat162 p0 = __floats2bfloat162_rn(ra[s].x, ra[s].y);
            __nv_bfloat162 p1 = __floats2bfloat162_rn(ra[s].z, ra[s].w);
            __nv_bfloat162* d = (__nv_bfloat162*)(A_sm + adst[s]);
            d[0] = p0; d[1] = p1;
        }
        #pragma unroll
        for (int s = 0; s < 4; s++) {
            if (bact[s]) {
                float4 v = bzero[s] ? make_float4(0.f,0.f,0.f,0.f) : rbv[s];
                __nv_bfloat162 p0 = __floats2bfloat162_rn(v.x, v.y);
                __nv_bfloat162 p1 = __floats2bfloat162_rn(v.z, v.w);
                __nv_bfloat162* d = (__nv_bfloat162*)(B_sm + bdst[s]);
                d[0] = p0; d[1] = p1;
            }
        }
        __syncthreads();
        if (ch + 1 < 4) {
            #pragma unroll
            for (int s = 0; s < 8; s++) ra[s] = *(const float4*)(asrc[s] + (ch + 1) * 64);
            #pragma unroll
            for (int s = 0; s < 4; s++) if (bact[s]) rbv[s] = *(const float4*)(bsrc[s] + (ch + 1) * 64);
        }
        #pragma unroll
        for (int st = 0; st < 4; st++) {
            int baseu = st * 8;
            int ai = (warp * 16 + (lane >> 2)) * 36 + baseu + (lane & 3);
            unsigned a0 = Au[ai];
            unsigned a1 = Au[ai + 8 * 36];
            unsigned a2 = Au[ai + 4];
            unsigned a3 = Au[ai + 8 * 36 + 4];
            #pragma unroll
            for (int j = 0; j < 7; j++) {
                int bidx = (j * 8 + (lane >> 2)) * 36 + baseu + (lane & 3);
                unsigned bb0 = Bu[bidx];
                unsigned bb1 = Bu[bidx + 4];
                asm volatile(
                    "mma.sync.aligned.m16n8k16.row.col.f32.bf16.bf16.f32 "
                    "{%0,%1,%2,%3}, {%4,%5,%6,%7}, {%8,%9}, {%0,%1,%2,%3};\n"
                    : "+f"(acc[j][0]), "+f"(acc[j][1]), "+f"(acc[j][2]), "+f"(acc[j][3])
                    : "r"(a0), "r"(a1), "r"(a2), "r"(a3), "r"(bb0), "r"(bb1));
            }
        }
        __syncthreads();
    }

    #pragma unroll
    for (int j = 0; j < 7; j++) {
        int r = warp * 16 + (lane >> 2);
        int c = j * 8 + 2 * (lane & 3);
        P[r][c]         = acc[j][0];
        P[r][c + 1]     = acc[j][1];
        P[r + 8][c]     = acc[j][2];
        P[r + 8][c + 1] = acc[j][3];
    }
    __syncthreads();
    for (int idx = tid; idx < 128 * LR; idx += 256) {
        int row = idx / LR, k = idx - row * LR;
        dst[(size_t)(b0 + row) * LR + k] = P[row][k];
    }
}

// ---------------------------------------------------------------------------
// Kernel 2: ONE batch per CTA (M=64 pad of 49), grid 2048, block 256.
// 2 CTAs/SM pinned via 80KB dyn smem -> concurrent V footprint
// 296 x 401KB = 119MB <= L2 -> pass-2 V re-reads hit L2.
// 8 warps = 4 m-strips x 2 n-halves. Fused reduction + softmax + c_t + out.
// ---------------------------------------------------------------------------
__global__ __launch_bounds__(256) void k2(
    const float* __restrict__ V, const float* __restrict__ h_t,
    const float* __restrict__ s_t, const float* __restrict__ w_h,
    const float* __restrict__ w_h_s, float* __restrict__ out)
{
    extern __shared__ __align__(16) unsigned char smraw[];

    const int tid = threadIdx.x;
    const int warp = tid >> 5, lane = tid & 31;
    const int wm = warp & 3;          // m-strip (rows wm*16..+15)
    const int wn = warp >> 2;         // n-half  (cols wn*32..)
    const int b = blockIdx.x;

    __nv_bfloat16* A_sm = (__nv_bfloat16*)smraw;             // 64 x 72 bf16
    __nv_bfloat16* B_sm = (__nv_bfloat16*)(smraw + 9216);    // 64 x 72 bf16
    unsigned* Au = (unsigned*)A_sm;
    unsigned* Bu = (unsigned*)B_sm;
    float (*Wv)[57] = (float (*)[57])smraw;                  // 64 x 57 fp32 (alias)
    float* gk      = (float*)(smraw + 18432);   // [64]
    float* wh      = (float*)(smraw + 18688);   // [64]
    float* zsm     = (float*)(smraw + 18944);   // [64]
    float* alpha_s = (float*)(smraw + 19200);   // [64]
    float* bet     = (float*)(smraw + 19456);   // [1]
    float* ssm     = (float*)(smraw + 19472);   // [64]

    // zero A/B tiles (pad rows/cols stay zero)
    for (int i = tid; i < 18432 / 4; i += 256) ((unsigned*)smraw)[i] = 0u;

    const float* Vb = V + (size_t)b * LR * DIM;

    // staging slots: A 784 float4 (49 rows x 16), B 392 uint4 (49 rows x 8)
    const float* asrc[4]; int adst[4]; bool aact[4];
    #pragma unroll
    for (int s = 0; s < 4; s++) {
        int a = s * 256 + tid;
        aact[s] = (a < 784);
        int row = aact[s] ? (a >> 4) : 0;
        int c4  = aact[s] ? (a & 15) : 0;
        asrc[s] = Vb + (size_t)row * DIM + c4 * 4;
        adst[s] = row * 72 + c4 * 4;
    }
    const __nv_bfloat16* bsrc[2]; int bdst[2]; bool bact[2];
    #pragma unroll
    for (int s = 0; s < 2; s++) {
        int idx = s * 256 + tid;
        bact[s] = (idx < 392);
        int row = bact[s] ? (idx >> 3) : 0;
        int q   = bact[s] ? (idx & 7) : 0;
        bsrc[s] = wv_bf + (size_t)row * DIM + q * 8;
        bdst[s] = row * 72 + q * 8;
    }

    float acc[4][4];
    #pragma unroll
    for (int j = 0; j < 4; j++) { acc[j][0]=acc[j][1]=acc[j][2]=acc[j][3]=0.f; }

    float4 ra[4]; uint4 rb[2];
    #pragma unroll
    for (int s = 0; s < 4; s++) if (aact[s]) ra[s] = *(const float4*)(asrc[s]);
    #pragma unroll
    for (int s = 0; s < 2; s++) if (bact[s]) rb[s] = *(const uint4*)(bsrc[s]);

    __syncthreads();   // zero-fill complete

    #pragma unroll 1
    for (int ch = 0; ch < 32; ch++) {
        #pragma unroll
        for (int s = 0; s < 4; s++) {
            if (aact[s]) {
                __nv_bfloat162 p0 = __floats2bfloat162_rn(ra[s].x, ra[s].y);
                __nv_bfloat162 p1 = __floats2bfloat162_rn(ra[s].z, ra[s].w);
                __nv_bfloat162* d = (__nv_bfloat162*)(A_sm + adst[s]);
                d[0] = p0; d[1] = p1;
            }
        }
        #pragma unroll
        for (int s = 0; s < 2; s++)
            if (bact[s]) *(uint4*)(B_sm + bdst[s]) = rb[s];
        __syncthreads();

        if (ch + 1 < 32) {
            #pragma unroll
            for (int s = 0; s < 4; s++)
                if (aact[s]) ra[s] = *(const float4*)(asrc[s] + (ch + 1) * 64);
            #pragma unroll
            for (int s = 0; s < 2; s++)
                if (bact[s]) rb[s] = *(const uint4*)(bsrc[s] + (ch + 1) * 64);
        }

        #pragma unroll
        for (int st = 0; st < 4; st++) {
            int baseu = st * 8;
            int ai = (wm * 16 + (lane >> 2)) * 36 + baseu + (lane & 3);
            unsigned a0 = Au[ai];
            unsigned a1 = Au[ai + 8 * 36];
            unsigned a2 = Au[ai + 4];
            unsigned a3 = Au[ai + 8 * 36 + 4];
            #pragma unroll
            for (int j = 0; j < 4; j++) {
                if (wn == 1 && j == 3) continue;   // N=56: cols 0..55 only
                int bidx = (wn * 32 + j * 8 + (lane >> 2)) * 36 + baseu + (lane & 3);
                unsigned bb0 = Bu[bidx];
                unsigned bb1 = Bu[bidx + 4];
                asm volatile(
                    "mma.sync.aligned.m16n8k16.row.col.f32.bf16.bf16.f32 "
                    "{%0,%1,%2,%3}, {%4,%5,%6,%7}, {%8,%9}, {%0,%1,%2,%3};\n"
                    : "+f"(acc[j][0]), "+f"(acc[j][1]), "+f"(acc[j][2]), "+f"(acc[j][3])
                    : "r"(a0), "r"(a1), "r"(a2), "r"(a3), "r"(bb0), "r"(bb1));
            }
        }
        __syncthreads();
    }

    // ---- epilogue: accs -> Wv (alias) ----
    #pragma unroll
    for (int j = 0; j < 4; j++) {
        if (wn == 1 && j == 3) continue;
        int r = wm * 16 + (lane >> 2);
        int c = wn * 32 + j * 8 + 2 * (lane & 3);
        Wv[r][c]         = acc[j][0];
        Wv[r][c + 1]     = acc[j][1];
        Wv[r + 8][c]     = acc[j][2];
        Wv[r + 8][c + 1] = acc[j][3];
    }
    // inline split-K reduction for this batch
    if (tid < LR) {
        float g = 0.f, S = 0.f;
        #pragma unroll
        for (int i = 0; i < 8; i++) {
            g += part_scr[((size_t)i * BATCH + b) * LR + tid];
            S += part_scr[((size_t)(8 + i) * BATCH + b) * LR + tid];
        }
        gk[tid]  = g;
        ssm[tid] = tanhf(g + S) * w_h_s[tid];
        wh[tid]  = w_h[tid];
    }
    __syncthreads();

    // z[l] = sum_k tanh(Wv[l,k] + g[k]) * w_h[k] ; 4 threads per row
    {
        int row = tid >> 2, q = tid & 3;
        float z = 0.f;
        for (int k = q; k < LR; k += 4)
            z += tanhf(Wv[row][k] + gk[k]) * wh[k];
        z += __shfl_xor_sync(0xffffffffu, z, 1);
        z += __shfl_xor_sync(0xffffffffu, z, 2);
        if (q == 0) zsm[row] = z;
    }
    __syncthreads();

    // softmax over 50 logits in warp 0
    if (warp == 0) {
        float sp = (lane < LR) ? ssm[lane] : 0.f;
        if (lane + 32 < LR) sp += ssm[lane + 32];
        #pragma unroll
        for (int o = 16; o > 0; o >>= 1) sp += __shfl_xor_sync(0xffffffffu, sp, o);
        float sent = sp;

        float v0 = (lane < LR) ? zsm[lane] : -1e30f;
        float v1 = -1e30f;
        if (lane + 32 < LR)       v1 = zsm[lane + 32];
        else if (lane + 32 == LR) v1 = sent;
        float m = fmaxf(v0, v1);
        #pragma unroll
        for (int o = 16; o > 0; o >>= 1) m = fmaxf(m, __shfl_xor_sync(0xffffffffu, m, o));
        float e0 = __expf(v0 - m), e1 = __expf(v1 - m);
        float s = e0 + e1;
        #pragma unroll
        for (int o = 16; o > 0; o >>= 1) s += __shfl_xor_sync(0xffffffffu, s, o);
        float inv = 1.f / s;
        if (lane < LR)       alpha_s[lane]      = e0 * inv;
        if (lane + 32 < LR)  alpha_s[lane + 32] = e1 * inv;
        if (lane == 17)      bet[0] = e1 * inv;   // logit index 49
    }
    __syncthreads();

    // pass 2: c_t + output (V re-read, L2-resident)
    {
        float be = bet[0];
        float om = 1.f - be;
        float c0x = 0.f, c0y = 0.f, c0z = 0.f, c0w = 0.f;
        float c1x = 0.f, c1y = 0.f, c1z = 0.f, c1w = 0.f;
        #pragma unroll 7
        for (int l = 0; l < LR; l++) {
            float a = alpha_s[l];
            float4 v0 = *(const float4*)(Vb + (size_t)l * DIM + tid * 4);
            float4 v1 = *(const float4*)(Vb + (size_t)l * DIM + 1024 + tid * 4);
            c0x += a * v0.x; c0y += a * v0.y; c0z += a * v0.z; c0w += a * v0.w;
            c1x += a * v1.x; c1y += a * v1.y; c1z += a * v1.z; c1w += a * v1.w;
        }
        {
            float4 s4 = *(const float4*)(s_t + (size_t)b * DIM + tid * 4);
            float4 h4 = *(const float4*)(h_t + (size_t)b * DIM + tid * 4);
            float4 o;
            o.x = be * s4.x + om * c0x + h4.x;
            o.y = be * s4.y + om * c0y + h4.y;
            o.z = be * s4.z + om * c0z + h4.z;
            o.w = be * s4.w + om * c0w + h4.w;
            *(float4*)(out + (size_t)b * DIM + tid * 4) = o;
        }
        {
            float4 s4 = *(const float4*)(s_t + (size_t)b * DIM + 1024 + tid * 4);
            float4 h4 = *(const float4*)(h_t + (size_t)b * DIM + 1024 + tid * 4);
            float4 o;
            o.x = be * s4.x + om * c1x + h4.x;
            o.y = be * s4.y + om * c1y + h4.y;
            o.z = be * s4.z + om * c1z + h4.z;
            o.w = be * s4.w + om * c1w + h4.w;
            *(float4*)(out + (size_t)b * DIM + 1024 + tid * 4) = o;
        }
    }
}

extern "C" void kernel_launch(void* const* d_in, const int* in_sizes, int n_in,
                              void* d_out, int out_size) {
    const float* V     = (const float*)d_in[0];
    const float* h_t   = (const float*)d_in[1];
    const float* s_t   = (const float*)d_in[2];
    const float* W_v   = (const float*)d_in[3];
    const float* W_g   = (const float*)d_in[4];
    const float* W_s   = (const float*)d_in[5];
    const float* w_h   = (const float*)d_in[6];
    const float* w_h_s = (const float*)d_in[7];
    float* out = (float*)d_out;

    // 80KB dyn smem pins k2 at 2 CTAs/SM (16 warps) so the concurrent V
    // working set (296 x 401KB = 119MB) fits L2 for the pass-2 re-read.
    cudaFuncSetAttribute(k2, cudaFuncAttributeMaxDynamicSharedMemorySize, 81920);

    k1<<<256, 256>>>(h_t, s_t, W_v, W_g, W_s);
    k2<<<2048, 256, 81920>>>(V, h_t, s_t, w_h, w_h_s, out);
}